// round 2
// baseline (speedup 1.0000x reference)
#include <cuda_runtime.h>
#include <cstdint>

// Problem constants
constexpr int B = 8;
constexpr int S = 4096;
constexpr int D = 2048;
constexpr int E = 64;

// Reduction tiling
constexpr int SCHUNKS = 128;            // partial-sum chunks over S
constexpr int SPC     = S / SCHUNKS;    // 32 rows per chunk
constexpr int DTILES  = 2;              // 2048 d -> 2 tiles of 1024 (256 thr * float4)
constexpr int THR1    = 256;

// Static scratch (allocation-free rule): SCHUNKS * B * D floats = 8 MB
__device__ float g_partial[(size_t)SCHUNKS * B * D];

// ---------------------------------------------------------------------------
// Kernel 1: partial mean-pool sums. Each block: one (s-chunk, b, d-tile).
// Coalesced float4 loads; deterministic (no atomics).
// ---------------------------------------------------------------------------
__global__ __launch_bounds__(THR1) void partial_sum_kernel(const float* __restrict__ x) {
    int bid   = blockIdx.x;
    int chunk = bid / (B * DTILES);
    int rem   = bid % (B * DTILES);
    int b     = rem / DTILES;
    int dt    = rem % DTILES;
    int d     = dt * (THR1 * 4) + threadIdx.x * 4;

    const float4* __restrict__ xp =
        (const float4*)(x + ((size_t)b * S + (size_t)chunk * SPC) * D + d);
    const int stride4 = D / 4;  // float4 stride between consecutive s rows

    float4 acc = make_float4(0.f, 0.f, 0.f, 0.f);
#pragma unroll 8
    for (int s = 0; s < SPC; s++) {
        float4 v = xp[(size_t)s * stride4];
        acc.x += v.x; acc.y += v.y; acc.z += v.z; acc.w += v.w;
    }
    *(float4*)(g_partial + (size_t)chunk * (B * D) + (size_t)b * D + d) = acc;
}

// ---------------------------------------------------------------------------
// Kernel 2: per-batch. Fold partials -> mean vector in smem, GEMV vs W (one
// warp computes 4 experts via shuffle-reduce), then top-2 + softmax.
// Output: out[0..15] = weights[B][2], out[16..31] = (float)indices[B][2].
// ---------------------------------------------------------------------------
__global__ __launch_bounds__(512) void finalize_kernel(const float* __restrict__ W,
                                                       const float* __restrict__ bias,
                                                       float* __restrict__ out) {
    __shared__ float xf[D];
    __shared__ float logits[E];

    int b    = blockIdx.x;
    int tid  = threadIdx.x;
    int lane = tid & 31;
    int wid  = tid >> 5;  // 0..15

    // Fold the SCHUNKS partials for this batch's 2048 dims (each thread: 4 dims)
    {
        float4 acc = make_float4(0.f, 0.f, 0.f, 0.f);
        const float* base = g_partial + (size_t)b * D + tid * 4;
#pragma unroll 4
        for (int c = 0; c < SCHUNKS; c++) {
            float4 v = *(const float4*)(base + (size_t)c * (B * D));
            acc.x += v.x; acc.y += v.y; acc.z += v.z; acc.w += v.w;
        }
        const float inv = 1.0f / (float)S;
        xf[tid * 4 + 0] = acc.x * inv;
        xf[tid * 4 + 1] = acc.y * inv;
        xf[tid * 4 + 2] = acc.z * inv;
        xf[tid * 4 + 3] = acc.w * inv;
    }
    __syncthreads();

    // GEMV: 16 warps, each warp handles 4 experts
#pragma unroll
    for (int j = 0; j < 4; j++) {
        int e = wid * 4 + j;
        const float4* __restrict__ wp = (const float4*)(W + (size_t)e * D);
        float sum = 0.f;
#pragma unroll
        for (int i = 0; i < (D / 4) / 32; i++) {  // 16 float4 per lane
            int idx   = lane + i * 32;
            float4 w4 = wp[idx];
            float4 x4 = *(const float4*)(xf + idx * 4);
            sum += w4.x * x4.x + w4.y * x4.y + w4.z * x4.z + w4.w * x4.w;
        }
#pragma unroll
        for (int o = 16; o > 0; o >>= 1) sum += __shfl_xor_sync(0xffffffffu, sum, o);
        if (lane == 0) logits[e] = sum + bias[e];
    }
    __syncthreads();

    // Top-2 (strict > keeps lowest index on ties, matching jax.lax.top_k) + softmax
    if (tid == 0) {
        float v1 = -1e30f, v2 = -1e30f;
        int   i1 = 0, i2 = 0;
#pragma unroll
        for (int e = 0; e < E; e++) {
            float v = logits[e];
            if (v > v1) { v2 = v1; i2 = i1; v1 = v; i1 = e; }
            else if (v > v2) { v2 = v; i2 = e; }
        }
        float e2 = __expf(v2 - v1);     // softmax over {v1, v2}, stable at max
        float denom = 1.0f + e2;
        out[b * 2 + 0]      = 1.0f / denom;
        out[b * 2 + 1]      = e2 / denom;
        out[16 + b * 2 + 0] = (float)i1;
        out[16 + b * 2 + 1] = (float)i2;
    }
}

extern "C" void kernel_launch(void* const* d_in, const int* in_sizes, int n_in,
                              void* d_out, int out_size) {
    const float* x    = (const float*)d_in[0];  // [B, S, D] fp32
    const float* W    = (const float*)d_in[1];  // [E, D]   fp32
    const float* bias = (const float*)d_in[2];  // [E]      fp32
    float* out        = (float*)d_out;          // 32 floats: weights then indices

    partial_sum_kernel<<<SCHUNKS * B * DTILES, THR1>>>(x);
    finalize_kernel<<<B, 512>>>(W, bias, out);
}

// round 4
// speedup vs baseline: 1.2180x; 1.2180x over previous
#include <cuda_runtime.h>
#include <cstdint>

// Problem constants
constexpr int B = 8;
constexpr int S = 4096;
constexpr int D = 2048;
constexpr int E = 64;

// Reduction tiling
constexpr int SCHUNKS = 32;             // partial-sum chunks over S (was 128)
constexpr int SPC     = S / SCHUNKS;    // 128 rows per chunk
constexpr int DTILES  = 2;              // 2048 d -> 2 tiles of 1024 (256 thr * float4)
constexpr int THR1    = 256;

// Static scratch (allocation-free rule): SCHUNKS * B * D floats = 2 MB
__device__ float g_partial[(size_t)SCHUNKS * B * D];

// ---------------------------------------------------------------------------
// Kernel 1: partial mean-pool sums. Each block: one (s-chunk, b, d-tile).
// Coalesced float4 loads; deterministic (no atomics). Grid = 512 blocks.
// ---------------------------------------------------------------------------
__global__ __launch_bounds__(THR1) void partial_sum_kernel(const float* __restrict__ x) {
    int bid   = blockIdx.x;
    int chunk = bid / (B * DTILES);
    int rem   = bid % (B * DTILES);
    int b     = rem / DTILES;
    int dt    = rem % DTILES;
    int d     = dt * (THR1 * 4) + threadIdx.x * 4;

    const float4* __restrict__ xp =
        (const float4*)(x + ((size_t)b * S + (size_t)chunk * SPC) * D + d);
    const int stride4 = D / 4;  // float4 stride between consecutive s rows

    float4 acc = make_float4(0.f, 0.f, 0.f, 0.f);
#pragma unroll 8
    for (int s = 0; s < SPC; s++) {
        float4 v = xp[(size_t)s * stride4];
        acc.x += v.x; acc.y += v.y; acc.z += v.z; acc.w += v.w;
    }
    *(float4*)(g_partial + (size_t)chunk * (B * D) + (size_t)b * D + d) = acc;
}

// ---------------------------------------------------------------------------
// Kernel 2: per-batch. Fold partials (32 chunks, fully unrolled -> MLP=32),
// GEMV vs W (one warp computes 4 experts via shuffle-reduce), top-2 + softmax.
// Output: out[0..15] = weights[B][2], out[16..31] = (float)indices[B][2].
// ---------------------------------------------------------------------------
__global__ __launch_bounds__(512) void finalize_kernel(const float* __restrict__ W,
                                                       const float* __restrict__ bias,
                                                       float* __restrict__ out) {
    __shared__ float xf[D];
    __shared__ float logits[E];

    int b    = blockIdx.x;
    int tid  = threadIdx.x;
    int lane = tid & 31;
    int wid  = tid >> 5;  // 0..15

    // Fold the SCHUNKS partials for this batch (each thread: 4 dims = 1 float4).
    // Fully unrolled: 32 independent loads in flight per thread.
    {
        float4 acc = make_float4(0.f, 0.f, 0.f, 0.f);
        const float* base = g_partial + (size_t)b * D + tid * 4;
#pragma unroll
        for (int c = 0; c < SCHUNKS; c++) {
            float4 v = *(const float4*)(base + (size_t)c * (B * D));
            acc.x += v.x; acc.y += v.y; acc.z += v.z; acc.w += v.w;
        }
        const float inv = 1.0f / (float)S;
        xf[tid * 4 + 0] = acc.x * inv;
        xf[tid * 4 + 1] = acc.y * inv;
        xf[tid * 4 + 2] = acc.z * inv;
        xf[tid * 4 + 3] = acc.w * inv;
    }
    __syncthreads();

    // GEMV: 16 warps, each warp handles 4 experts
#pragma unroll
    for (int j = 0; j < 4; j++) {
        int e = wid * 4 + j;
        const float4* __restrict__ wp = (const float4*)(W + (size_t)e * D);
        float sum = 0.f;
#pragma unroll
        for (int i = 0; i < (D / 4) / 32; i++) {  // 16 float4 per lane
            int idx   = lane + i * 32;
            float4 w4 = wp[idx];
            float4 x4 = *(const float4*)(xf + idx * 4);
            sum += w4.x * x4.x + w4.y * x4.y + w4.z * x4.z + w4.w * x4.w;
        }
#pragma unroll
        for (int o = 16; o > 0; o >>= 1) sum += __shfl_xor_sync(0xffffffffu, sum, o);
        if (lane == 0) logits[e] = sum + bias[e];
    }
    __syncthreads();

    // Top-2 (strict > keeps lowest index on ties, matching jax.lax.top_k) + softmax
    if (tid == 0) {
        float v1 = -1e30f, v2 = -1e30f;
        int   i1 = 0, i2 = 0;
#pragma unroll
        for (int e = 0; e < E; e++) {
            float v = logits[e];
            if (v > v1) { v2 = v1; i2 = i1; v1 = v; i1 = e; }
            else if (v > v2) { v2 = v; i2 = e; }
        }
        float e2 = __expf(v2 - v1);     // softmax over {v1, v2}, stable at max
        float denom = 1.0f + e2;
        out[b * 2 + 0]      = 1.0f / denom;
        out[b * 2 + 1]      = e2 / denom;
        out[16 + b * 2 + 0] = (float)i1;
        out[16 + b * 2 + 1] = (float)i2;
    }
}

extern "C" void kernel_launch(void* const* d_in, const int* in_sizes, int n_in,
                              void* d_out, int out_size) {
    const float* x    = (const float*)d_in[0];  // [B, S, D] fp32
    const float* W    = (const float*)d_in[1];  // [E, D]   fp32
    const float* bias = (const float*)d_in[2];  // [E]      fp32
    float* out        = (float*)d_out;          // 32 floats: weights then indices

    partial_sum_kernel<<<SCHUNKS * B * DTILES, THR1>>>(x);
    finalize_kernel<<<B, 512>>>(W, bias, out);
}

// round 7
// speedup vs baseline: 1.2671x; 1.0403x over previous
#include <cuda_runtime.h>
#include <cstdint>

// Problem constants
constexpr int B = 8;
constexpr int S = 4096;
constexpr int D = 2048;
constexpr int E = 64;

// Reduction tiling
constexpr int SCHUNKS = 32;             // partial-sum chunks over S
constexpr int SPC     = S / SCHUNKS;    // 128 rows per chunk
constexpr int DTILES  = 2;              // 2048 d -> 2 tiles of 1024 (256 thr * float4)
constexpr int THR1    = 256;

// Static scratch (allocation-free rule)
__device__ float g_partial[(size_t)SCHUNKS * B * D];  // 2 MB
__device__ float g_mean[B * D];                       // 64 KB
__device__ float g_logits[B * E];                     // 2 KB

// ---------------------------------------------------------------------------
// Kernel 1: partial mean-pool sums. Each block: one (s-chunk, b, d-tile).
// Coalesced float4 loads; deterministic (no atomics). Grid = 512 blocks.
// ---------------------------------------------------------------------------
__global__ __launch_bounds__(THR1) void partial_sum_kernel(const float* __restrict__ x) {
    int bid   = blockIdx.x;
    int chunk = bid / (B * DTILES);
    int rem   = bid % (B * DTILES);
    int b     = rem / DTILES;
    int dt    = rem % DTILES;
    int d     = dt * (THR1 * 4) + threadIdx.x * 4;

    const float4* __restrict__ xp =
        (const float4*)(x + ((size_t)b * S + (size_t)chunk * SPC) * D + d);
    const int stride4 = D / 4;  // float4 stride between consecutive s rows

    float4 acc = make_float4(0.f, 0.f, 0.f, 0.f);
#pragma unroll 8
    for (int s = 0; s < SPC; s++) {
        float4 v = xp[(size_t)s * stride4];
        acc.x += v.x; acc.y += v.y; acc.z += v.z; acc.w += v.w;
    }
    *(float4*)(g_partial + (size_t)chunk * (B * D) + (size_t)b * D + d) = acc;
}

// ---------------------------------------------------------------------------
// Kernel 2: fold the 32 chunk-partials into the mean vector [B, D].
// Grid = 32 blocks x 128 threads = 4096 threads, one float4 each, 32
// fully-unrolled independent loads per thread (full MLP, 32 SMs busy).
// ---------------------------------------------------------------------------
__global__ __launch_bounds__(128) void fold_kernel() {
    int t = blockIdx.x * 128 + threadIdx.x;   // 0 .. 4095 (float4 index over B*D)
    const float* base = g_partial + (size_t)t * 4;

    float4 acc = make_float4(0.f, 0.f, 0.f, 0.f);
#pragma unroll
    for (int c = 0; c < SCHUNKS; c++) {
        float4 v = *(const float4*)(base + (size_t)c * (B * D));
        acc.x += v.x; acc.y += v.y; acc.z += v.z; acc.w += v.w;
    }
    const float inv = 1.0f / (float)S;
    float4 m = make_float4(acc.x * inv, acc.y * inv, acc.z * inv, acc.w * inv);
    *(float4*)(g_mean + (size_t)t * 4) = m;
}

// ---------------------------------------------------------------------------
// Kernel 3: GEMV. Grid = 64 blocks (one per expert), 8 warps = 8 batches.
// Each warp: dot(mean[b], W[e]) over D=2048 (16 float4/lane) + shuffle reduce.
// W row (8 KB) is L1-resident after first touch; means are L2-hot.
// ---------------------------------------------------------------------------
__global__ __launch_bounds__(256) void gemv_kernel(const float* __restrict__ W,
                                                   const float* __restrict__ bias) {
    int e    = blockIdx.x;
    int lane = threadIdx.x & 31;
    int b    = threadIdx.x >> 5;   // 0..7

    const float4* __restrict__ wp = (const float4*)(W + (size_t)e * D);
    const float4* __restrict__ xp = (const float4*)(g_mean + (size_t)b * D);

    float sum = 0.f;
#pragma unroll
    for (int i = 0; i < (D / 4) / 32; i++) {   // 16 float4 per lane
        int idx   = lane + i * 32;
        float4 w4 = wp[idx];
        float4 x4 = xp[idx];
        sum += w4.x * x4.x + w4.y * x4.y + w4.z * x4.z + w4.w * x4.w;
    }
#pragma unroll
    for (int o = 16; o > 0; o >>= 1) sum += __shfl_xor_sync(0xffffffffu, sum, o);
    if (lane == 0) g_logits[b * E + e] = sum + bias[e];
}

// ---------------------------------------------------------------------------
// Kernel 4: top-2 + softmax per batch. 1 block, 8 threads.
// Strict > keeps lowest index on ties (matches jax.lax.top_k).
// Output: out[0..15] = weights[B][2], out[16..31] = (float)indices[B][2].
// ---------------------------------------------------------------------------
__global__ __launch_bounds__(8) void top2_kernel(float* __restrict__ out) {
    int b = threadIdx.x;
    const float* lg = g_logits + b * E;

    float v1 = -1e30f, v2 = -1e30f;
    int   i1 = 0, i2 = 0;
#pragma unroll
    for (int e = 0; e < E; e++) {
        float v = lg[e];
        if (v > v1) { v2 = v1; i2 = i1; v1 = v; i1 = e; }
        else if (v > v2) { v2 = v; i2 = e; }
    }
    float e2 = __expf(v2 - v1);     // softmax over {v1, v2}, stable at max
    float denom = 1.0f + e2;
    out[b * 2 + 0]      = 1.0f / denom;
    out[b * 2 + 1]      = e2 / denom;
    out[16 + b * 2 + 0] = (float)i1;
    out[16 + b * 2 + 1] = (float)i2;
}

extern "C" void kernel_launch(void* const* d_in, const int* in_sizes, int n_in,
                              void* d_out, int out_size) {
    const float* x    = (const float*)d_in[0];  // [B, S, D] fp32
    const float* W    = (const float*)d_in[1];  // [E, D]   fp32
    const float* bias = (const float*)d_in[2];  // [E]      fp32
    float* out        = (float*)d_out;          // 32 floats: weights then indices

    partial_sum_kernel<<<SCHUNKS * B * DTILES, THR1>>>(x);
    fold_kernel<<<SCHUNKS, 128>>>();
    gemv_kernel<<<E, 256>>>(W, bias);
    top2_kernel<<<1, 8>>>(out);
}